// round 12
// baseline (speedup 1.0000x reference)
#include <cuda_runtime.h>
#include <cuda_fp16.h>
#include <math.h>
#include <stdint.h>

// Problem constants
#define NB 8
#define LL 2048
#define NTOK (NB*LL)        // 16384
#define DD 1024
#define EE 8
#define HH 2048

#define BM 128
#define BN 256
#define BK 128
#define NSTAGE 2
#define ROWB 256                // bytes per smem row (128 fp16)
#define ATILE_BYTES (128*ROWB)  // 32768
#define BTILE_BYTES (256*ROWB)  // 65536
#define STAGE_BYTES (ATILE_BYTES + BTILE_BYTES)   // 98304
#define OFF_B ATILE_BYTES
#define OFF_TOK 0
#define OFF_TILE 1024
#define SMEM_TOTAL (OFF_TILE + NSTAGE * STAGE_BYTES)   // 197632 (1 CTA/SM)

// -------------------- device scratch (no allocs allowed) --------------------
__device__ __half g_xh[(size_t)NTOK * DD];
__device__ __half g_w1h[(size_t)EE * HH * DD];   // [E][H][D]  (W1^T)
__device__ __half g_w2h[(size_t)EE * DD * HH];   // [E][D][H]  (W2^T)
__device__ __half g_h[(size_t)NTOK * HH];        // permuted hidden
__device__ int   g_perm[NTOK];
__device__ int   g_topidx[NTOK];
__device__ float g_topw[NTOK];
__device__ int   g_counts[EE];   // zero at module load; scan re-zeros after use
__device__ int   g_offs[EE + 1];
__device__ int   g_cursor[EE];

// -------------------- PTX helpers (all non-'a' features) --------------------
__device__ __forceinline__ uint32_t smem_u32(const void* p) {
    uint32_t a;
    asm("{ .reg .u64 t; cvta.to.shared.u64 t, %1; cvt.u32.u64 %0, t; }" : "=r"(a) : "l"(p));
    return a;
}
__device__ __forceinline__ void cp16(uint32_t dst, const void* src) {
    asm volatile("cp.async.cg.shared.global [%0], [%1], 16;" :: "r"(dst), "l"(src));
}
#define CP_COMMIT() asm volatile("cp.async.commit_group;" ::: "memory")
#define CP_WAIT(n)  asm volatile("cp.async.wait_group %0;" :: "n"(n) : "memory")

__device__ __forceinline__ void ldsm4(uint32_t* r, uint32_t addr) {
    asm volatile("ldmatrix.sync.aligned.m8n8.x4.shared.b16 {%0,%1,%2,%3}, [%4];"
                 : "=r"(r[0]), "=r"(r[1]), "=r"(r[2]), "=r"(r[3]) : "r"(addr));
}
__device__ __forceinline__ void mma16816(float* c, const uint32_t* a, const uint32_t* b) {
    asm volatile("mma.sync.aligned.m16n8k16.row.col.f32.f16.f16.f32 "
        "{%0,%1,%2,%3}, {%4,%5,%6,%7}, {%8,%9}, {%0,%1,%2,%3};"
        : "+f"(c[0]), "+f"(c[1]), "+f"(c[2]), "+f"(c[3])
        : "r"(a[0]), "r"(a[1]), "r"(a[2]), "r"(a[3]), "r"(b[0]), "r"(b[1]));
}

// -------------------- gating (fused with x->fp16 conversion) --------------------
__global__ void gate_kernel(const float* __restrict__ x,
                            const float* __restrict__ Wg,
                            const float* __restrict__ bg,
                            float* __restrict__ gw_out) {
    int warp = threadIdx.x >> 5;
    int lane = threadIdx.x & 31;
    int t = blockIdx.x * 8 + warp;
    if (t >= NTOK) return;

    const float* xr = x + (size_t)t * DD;
    float xv[32];
#pragma unroll
    for (int i = 0; i < 32; i++) xv[i] = xr[lane + 32 * i];

    __half* xh = g_xh + (size_t)t * DD;
#pragma unroll
    for (int i = 0; i < 32; i++) xh[lane + 32 * i] = __float2half_rn(xv[i]);

    float logit[EE];
#pragma unroll
    for (int e = 0; e < EE; e++) {
        float s = 0.f;
#pragma unroll
        for (int i = 0; i < 32; i++) s += xv[i] * Wg[(lane + 32 * i) * EE + e];
#pragma unroll
        for (int o = 16; o > 0; o >>= 1) s += __shfl_xor_sync(0xffffffffu, s, o);
        logit[e] = s + bg[e];
    }

    if (lane == 0) {
        float mx = logit[0]; int bi = 0;
#pragma unroll
        for (int e = 1; e < EE; e++) if (logit[e] > mx) { mx = logit[e]; bi = e; }
        float p[EE]; float se = 0.f;
#pragma unroll
        for (int e = 0; e < EE; e++) { p[e] = expf(logit[e] - mx); se += p[e]; }
        float inv = 1.f / se;
#pragma unroll
        for (int e = 0; e < EE; e++) gw_out[(size_t)t * EE + e] = p[e] * inv;
        g_topidx[t] = bi;
        g_topw[t]  = p[bi] * inv;
        atomicAdd(&g_counts[bi], 1);
    }
}

// -------------------- scan: offsets + cursor, then re-zero counts ------------
__global__ void scan_kernel() {
    int s = 0;
    g_offs[0] = 0;
    for (int e = 0; e < EE; e++) {
        g_cursor[e] = s;
        s += g_counts[e];
        g_offs[e + 1] = s;
        g_counts[e] = 0;          // ready for next kernel_launch invocation
    }
}

// -------------------- prep: fused weight-convert/transpose + scatter ---------
__global__ void prep_kernel(const float* __restrict__ W1, const float* __restrict__ W2) {
    const int bid = blockIdx.x;
    const int tid = threadIdx.x;
    if (bid >= 65536) {
        int t = (bid - 65536) * 256 + tid;
        if (t < NTOK) {
            int e = g_topidx[t];
            int pos = atomicAdd(&g_cursor[e], 1);
            g_perm[pos] = t;
        }
        return;
    }
    const int bx = bid & 63, by = (bid >> 6) & 63, bz = bid >> 12;
    const float* src;
    __half* dh;
    int K, N;
    if (bz < EE) {
        src = W1 + (size_t)bz * DD * HH; dh = g_w1h + (size_t)bz * HH * DD;
        K = DD; N = HH;
        if (by >= K / 32) return;
    } else {
        int e = bz - EE;
        src = W2 + (size_t)e * HH * DD; dh = g_w2h + (size_t)e * DD * HH;
        K = HH; N = DD;
        if (bx >= N / 32) return;
    }
    __shared__ float t[32][33];
    const int tx = tid & 31, ty = tid >> 5;
    const int n0 = bx * 32, k0 = by * 32;
#pragma unroll
    for (int i = 0; i < 4; i++)
        t[ty + i * 8][tx] = src[(size_t)(k0 + ty + i * 8) * N + n0 + tx];
    __syncthreads();
#pragma unroll
    for (int i = 0; i < 4; i++) {
        float v = t[tx][ty + i * 8];
        size_t o = (size_t)(n0 + ty + i * 8) * K + (k0 + tx);
        dh[o] = __float2half_rn(v);
    }
}

// ------ mma.sync MoE GEMM (fp16), 128x256 tile, warp 64x64, BK=128 ----------
// SMEM rows 256B = 128 fp16 (k-dim), 16B chunks swizzled: chunk' = chunk ^ (row&7).
// 2-stage pipeline; per-SMSP warp pairs process k-steps in staggered order to
// anti-phase ldsm bursts against HMMA bursts.
#define LOAD_ROW(ptr, db) do { \
    _Pragma("unroll") \
    for (int _c2 = 0; _c2 < 16; _c2++) \
        cp16((db) + ((((uint32_t)_c2) ^ swr) << 4), (ptr) + _c2 * 8); \
} while (0)

#define LOAD_STAGE(c) do { \
    uint32_t so = OFF_TILE + ((c) & 1) * STAGE_BYTES; \
    LOAD_ROW(srcpB + (size_t)(c) * BK, S + so + OFF_B + (uint32_t)tid * ROWB); \
    if (tid < 128) LOAD_ROW(srcpA + (size_t)(c) * BK, S + so + (uint32_t)tid * ROWB); \
} while (0)

template<int MODE>
__global__ __launch_bounds__(256, 1)
void moe_gemm(const float* __restrict__ bias, float* __restrict__ out) {
    constexpr int KTOT = (MODE == 0) ? DD : HH;
    constexpr int NROW = (MODE == 0) ? HH : DD;
    constexpr int NCH  = KTOT / BK;       // 8 or 16

    const int e    = blockIdx.z;
    const int base = g_offs[e];
    const int cnt  = g_offs[e + 1] - base;
    const int m0   = blockIdx.y * BM;
    if (m0 >= cnt) return;
    const int n0   = blockIdx.x * BN;

    extern __shared__ char smem[];
    const uint32_t S = smem_u32(smem);
    int* tok = (int*)(smem + OFF_TOK);
    const int tid = threadIdx.x;

    if (tid < 128) {
        int m = m0 + tid; if (m >= cnt) m = cnt - 1;
        tok[tid] = g_perm[base + m];
    }
    __syncthreads();

    // ---- loader setup: every thread loads B row tid; tid<128 also A row tid --
    const __half* Abase = (MODE == 0) ? g_xh : g_h;
    const __half* Wbase = (MODE == 0) ? g_w1h : g_w2h;
    const uint32_t swr = (uint32_t)(tid & 7);
    const __half* srcpB = Wbase + ((size_t)e * NROW + n0 + tid) * KTOT;
    const __half* srcpA = nullptr;
    if (tid < 128) {
        size_t rowA;
        if (MODE == 0) rowA = (size_t)tok[tid];
        else { int m = m0 + tid; if (m >= cnt) m = cnt - 1; rowA = (size_t)(base + m); }
        srcpA = Abase + rowA * KTOT;
    }

    // ---- fragment addressing: 8 warps = 2 (M) x 4 (N), warp tile 64x64 ----
    const int lane = tid & 31, wid = tid >> 5;
    const int wm = wid >> 2, wn = wid & 3;
    const int soff = (wid >> 2) * 4;          // k-step stagger: SMSP pair anti-phase
    const uint32_t rA  = lane & 15;
    const uint32_t cA  = lane >> 4;
    const uint32_t swA = rA & 7;
    uint32_t rowA_s[4];
#pragma unroll
    for (int i = 0; i < 4; i++) rowA_s[i] = (uint32_t)(wm * 64 + i * 16 + rA) * ROWB;
    const uint32_t rB  = (lane & 7) | ((lane >> 1) & 8);
    const uint32_t cB  = (lane >> 3) & 1;
    const uint32_t swB = rB & 7;
    uint32_t rowB_s[4];
#pragma unroll
    for (int jj = 0; jj < 4; jj++) rowB_s[jj] = OFF_B + (uint32_t)(wn * 64 + jj * 16 + rB) * ROWB;

    float C[4][8][4];
#pragma unroll
    for (int i = 0; i < 4; i++)
#pragma unroll
        for (int j = 0; j < 8; j++)
#pragma unroll
            for (int q = 0; q < 4; q++) C[i][j][q] = 0.f;

    LOAD_STAGE(0); CP_COMMIT();

    for (int c = 0; c < NCH; c++) {
        CP_WAIT(0);
        __syncthreads();
        // safe: buffer (c+1)&1 == (c-1)&1; all warps finished compute(c-1)
        // before this barrier, and chunk c is fully resident (wait_group 0).
        if (c + 1 < NCH) { LOAD_STAGE(c + 1); }
        CP_COMMIT();

        const uint32_t buf = S + OFF_TILE + (uint32_t)(c & 1) * STAGE_BYTES;
#pragma unroll
        for (int s = 0; s < 8; s++) {          // 8 x k16 per 128-chunk, staggered
            const uint32_t ss = (uint32_t)((s + soff) & 7);
            const uint32_t kc = 2 * ss;
            uint32_t A[4][4], B[4][4];
#pragma unroll
            for (int i = 0; i < 4; i++)
                ldsm4(A[i], buf + rowA_s[i] + (((kc + cA) ^ swA) << 4));
#pragma unroll
            for (int jj = 0; jj < 4; jj++)
                ldsm4(B[jj], buf + rowB_s[jj] + (((kc + cB) ^ swB) << 4));
#pragma unroll
            for (int i = 0; i < 4; i++)
#pragma unroll
                for (int j = 0; j < 8; j++)
                    mma16816(C[i][j], A[i], &B[j >> 1][(j & 1) * 2]);
        }
    }

    // -------- epilogue --------
    const int gcol0 = n0 + wn * 64;
#pragma unroll
    for (int i = 0; i < 4; i++) {
        const int rbase = wm * 64 + i * 16 + (lane >> 2);
#pragma unroll
        for (int half = 0; half < 2; half++) {
            const int rr = rbase + 8 * half;
            const int m  = m0 + rr;
            if (m >= cnt) continue;
            if (MODE == 0) {
                const size_t pb = (size_t)(base + m) * HH;
#pragma unroll
                for (int j = 0; j < 8; j++) {
                    const int cc = gcol0 + j * 8 + (lane & 3) * 2;
                    float v0 = fmaxf(C[i][j][2 * half]     + bias[e * HH + cc],     0.f);
                    float v1 = fmaxf(C[i][j][2 * half + 1] + bias[e * HH + cc + 1], 0.f);
                    *(__half2*)(&g_h[pb + cc]) = __floats2half2_rn(v0, v1);
                }
            } else {
                const int t = tok[rr];
                const float w = g_topw[t];
                float* op = out + (size_t)t * DD;
#pragma unroll
                for (int j = 0; j < 8; j++) {
                    const int cc = gcol0 + j * 8 + (lane & 3) * 2;
                    float2 v;
                    v.x = w * (C[i][j][2 * half]     + bias[e * DD + cc]);
                    v.y = w * (C[i][j][2 * half + 1] + bias[e * DD + cc + 1]);
                    *(float2*)(op + cc) = v;
                }
            }
        }
    }
}

// -------------------- launch --------------------
extern "C" void kernel_launch(void* const* d_in, const int* in_sizes, int n_in,
                              void* d_out, int out_size) {
    const float* x  = (const float*)d_in[0];
    const float* Wg = (const float*)d_in[1];
    const float* bg = (const float*)d_in[2];
    const float* W1 = (const float*)d_in[3];
    const float* b1 = (const float*)d_in[4];
    const float* W2 = (const float*)d_in[5];
    const float* b2 = (const float*)d_in[6];
    float* out = (float*)d_out;
    float* gw  = out + (size_t)NTOK * DD;   // gate_weights appended after `out`

    cudaFuncSetAttribute(moe_gemm<0>, cudaFuncAttributeMaxDynamicSharedMemorySize, SMEM_TOTAL);
    cudaFuncSetAttribute(moe_gemm<1>, cudaFuncAttributeMaxDynamicSharedMemorySize, SMEM_TOTAL);

    gate_kernel<<<NTOK / 8, 256>>>(x, Wg, bg, gw);            // 1 (fused x->fp16 + counts)
    scan_kernel<<<1, 1>>>();                                  // 2 (offs/cursor + re-zero counts)
    prep_kernel<<<65600, 256>>>(W1, W2);                      // 3 (convw + scatter fused)
    moe_gemm<0><<<dim3(HH / BN, NTOK / BM, EE), 256, SMEM_TOTAL>>>(b1, nullptr);  // 4 <- ncu
    moe_gemm<1><<<dim3(DD / BN, NTOK / BM, EE), 256, SMEM_TOTAL>>>(b2, out);      // 5
}

// round 13
// speedup vs baseline: 1.0307x; 1.0307x over previous
#include <cuda_runtime.h>
#include <cuda_fp16.h>
#include <math.h>
#include <stdint.h>

// Problem constants
#define NB 8
#define LL 2048
#define NTOK (NB*LL)        // 16384
#define DD 1024
#define EE 8
#define HH 2048

#define BM 128
#define BN 256
#define BK 64
#define NSTAGE 3
#define ATILE_BYTES 16384       // 128 m-rows x 128B (k-major)
#define BTILE_BYTES 32768       // 64 k-rows x 512B (n-major)
#define STAGE_BYTES (ATILE_BYTES + BTILE_BYTES)   // 49152
#define OFF_B ATILE_BYTES
#define OFF_TOK 0
#define OFF_TILE 1024
#define SMEM_TOTAL (OFF_TILE + NSTAGE * STAGE_BYTES)   // 148480 (1 CTA/SM)

// -------------------- device scratch (no allocs allowed) --------------------
__device__ __half g_xh[(size_t)NTOK * DD];
__device__ __half g_w1h[(size_t)EE * DD * HH];   // [E][D][H]  (W1 as-is, K-major)
__device__ __half g_w2h[(size_t)EE * HH * DD];   // [E][H][D]  (W2 as-is, K-major)
__device__ __half g_h[(size_t)NTOK * HH];        // permuted hidden
__device__ int   g_perm[NTOK];
__device__ int   g_topidx[NTOK];
__device__ float g_topw[NTOK];
__device__ int   g_counts[EE];   // zero at module load; scan re-zeros after use
__device__ int   g_offs[EE + 1];
__device__ int   g_cursor[EE];

// -------------------- PTX helpers (all non-'a' features) --------------------
__device__ __forceinline__ uint32_t smem_u32(const void* p) {
    uint32_t a;
    asm("{ .reg .u64 t; cvta.to.shared.u64 t, %1; cvt.u32.u64 %0, t; }" : "=r"(a) : "l"(p));
    return a;
}
__device__ __forceinline__ void cp16(uint32_t dst, const void* src) {
    asm volatile("cp.async.cg.shared.global [%0], [%1], 16;" :: "r"(dst), "l"(src));
}
#define CP_COMMIT() asm volatile("cp.async.commit_group;" ::: "memory")
#define CP_WAIT(n)  asm volatile("cp.async.wait_group %0;" :: "n"(n) : "memory")

__device__ __forceinline__ void ldsm4(uint32_t* r, uint32_t addr) {
    asm volatile("ldmatrix.sync.aligned.m8n8.x4.shared.b16 {%0,%1,%2,%3}, [%4];"
                 : "=r"(r[0]), "=r"(r[1]), "=r"(r[2]), "=r"(r[3]) : "r"(addr));
}
__device__ __forceinline__ void ldsm4t(uint32_t* r, uint32_t addr) {
    asm volatile("ldmatrix.sync.aligned.m8n8.x4.trans.shared.b16 {%0,%1,%2,%3}, [%4];"
                 : "=r"(r[0]), "=r"(r[1]), "=r"(r[2]), "=r"(r[3]) : "r"(addr));
}
__device__ __forceinline__ void mma16816(float* c, const uint32_t* a, const uint32_t* b) {
    asm volatile("mma.sync.aligned.m16n8k16.row.col.f32.f16.f16.f32 "
        "{%0,%1,%2,%3}, {%4,%5,%6,%7}, {%8,%9}, {%0,%1,%2,%3};"
        : "+f"(c[0]), "+f"(c[1]), "+f"(c[2]), "+f"(c[3])
        : "r"(a[0]), "r"(a[1]), "r"(a[2]), "r"(a[3]), "r"(b[0]), "r"(b[1]));
}

// -------------------- gating (fused with x->fp16 conversion) --------------------
__global__ void gate_kernel(const float* __restrict__ x,
                            const float* __restrict__ Wg,
                            const float* __restrict__ bg,
                            float* __restrict__ gw_out) {
    int warp = threadIdx.x >> 5;
    int lane = threadIdx.x & 31;
    int t = blockIdx.x * 8 + warp;
    if (t >= NTOK) return;

    const float* xr = x + (size_t)t * DD;
    float xv[32];
#pragma unroll
    for (int i = 0; i < 32; i++) xv[i] = xr[lane + 32 * i];

    __half* xh = g_xh + (size_t)t * DD;
#pragma unroll
    for (int i = 0; i < 32; i++) xh[lane + 32 * i] = __float2half_rn(xv[i]);

    float logit[EE];
#pragma unroll
    for (int e = 0; e < EE; e++) {
        float s = 0.f;
#pragma unroll
        for (int i = 0; i < 32; i++) s += xv[i] * Wg[(lane + 32 * i) * EE + e];
#pragma unroll
        for (int o = 16; o > 0; o >>= 1) s += __shfl_xor_sync(0xffffffffu, s, o);
        logit[e] = s + bg[e];
    }

    if (lane == 0) {
        float mx = logit[0]; int bi = 0;
#pragma unroll
        for (int e = 1; e < EE; e++) if (logit[e] > mx) { mx = logit[e]; bi = e; }
        float p[EE]; float se = 0.f;
#pragma unroll
        for (int e = 0; e < EE; e++) { p[e] = expf(logit[e] - mx); se += p[e]; }
        float inv = 1.f / se;
#pragma unroll
        for (int e = 0; e < EE; e++) gw_out[(size_t)t * EE + e] = p[e] * inv;
        g_topidx[t] = bi;
        g_topw[t]  = p[bi] * inv;
        atomicAdd(&g_counts[bi], 1);
    }
}

// -------------------- scan: offsets + cursor, then re-zero counts ------------
__global__ void scan_kernel() {
    int s = 0;
    g_offs[0] = 0;
    for (int e = 0; e < EE; e++) {
        g_cursor[e] = s;
        s += g_counts[e];
        g_offs[e + 1] = s;
        g_counts[e] = 0;          // ready for next kernel_launch invocation
    }
}

// ----- prep: pure streaming fp32->fp16 weight convert (no transpose) + scatter
// blocks [0, 32768): convert (grid-stride float4), blocks [32768, 32832): scatter
#define NQUAD ((size_t)EE * DD * HH / 4)       // 4,194,304 float4 per weight
__global__ void prep_kernel(const float* __restrict__ W1, const float* __restrict__ W2) {
    const int bid = blockIdx.x;
    const int tid = threadIdx.x;
    if (bid >= 32768) {
        int t = (bid - 32768) * 256 + tid;
        if (t < NTOK) {
            int e = g_topidx[t];
            int pos = atomicAdd(&g_cursor[e], 1);
            g_perm[pos] = t;
        }
        return;
    }
    size_t i = (size_t)bid * 256 + tid;        // quad index over both weights
    const float4* src;
    __half2* dst;
    if (i < NQUAD) { src = (const float4*)W1; dst = (__half2*)g_w1h; }
    else           { src = (const float4*)W2; dst = (__half2*)g_w2h; i -= NQUAD; }
    float4 v = src[i];
    dst[i * 2]     = __floats2half2_rn(v.x, v.y);
    dst[i * 2 + 1] = __floats2half2_rn(v.z, v.w);
}

// ------ mma.sync MoE GEMM (fp16), 128x256 tile, warp 64x64, K-major B -------
// A tile: 128 m-rows x 128B (64 fp16 k), 16B chunks swizzled c^(row&7), ldsm.
// B tile: 64 k-rows x 512B (256 fp16 n), 16B chunks swizzled c^(krow&7), ldsm.trans.
template<int MODE>
__global__ __launch_bounds__(256, 1)
void moe_gemm(const float* __restrict__ bias, float* __restrict__ out) {
    constexpr int KTOT = (MODE == 0) ? DD : HH;   // B k-dim
    constexpr int NTOTW = (MODE == 0) ? HH : DD;  // B n-dim (row stride in gmem)
    constexpr int NCH  = KTOT / BK;               // 16 or 32

    const int e    = blockIdx.z;
    const int base = g_offs[e];
    const int cnt  = g_offs[e + 1] - base;
    const int m0   = blockIdx.y * BM;
    if (m0 >= cnt) return;
    const int n0   = blockIdx.x * BN;

    extern __shared__ char smem[];
    const uint32_t S = smem_u32(smem);
    int* tok = (int*)(smem + OFF_TOK);
    const int tid = threadIdx.x;

    if (tid < 128) {
        int m = m0 + tid; if (m >= cnt) m = cnt - 1;
        tok[tid] = g_perm[base + m];
    }
    __syncthreads();

    // ---- loader setup ----
    // B: all 256 threads: k-row krL = tid>>2 (0..63), quarter qL = tid&3 (128B)
    // A: threads 0-127: m-row tid (128B)
    const __half* Abase = (MODE == 0) ? g_xh : g_h;
    const __half* Wbase = (MODE == 0) ? g_w1h : g_w2h;
    const uint32_t krL  = (uint32_t)(tid >> 2);
    const uint32_t qL   = (uint32_t)(tid & 3);
    const uint32_t swzL = krL & 7;
    const uint32_t swrA = (uint32_t)(tid & 7);
    const __half* srcpB = Wbase + (size_t)e * KTOT * NTOTW + (size_t)krL * NTOTW + n0 + qL * 64;
    const __half* srcpA = nullptr;
    if (tid < 128) {
        size_t rowA;
        if (MODE == 0) rowA = (size_t)tok[tid];
        else { int m = m0 + tid; if (m >= cnt) m = cnt - 1; rowA = (size_t)(base + m); }
        srcpA = Abase + rowA * KTOT;
    }

#define LOAD_STAGE(c) do { \
    uint32_t so = S + OFF_TILE + ((c) % NSTAGE) * STAGE_BYTES; \
    { const __half* bs = srcpB + (size_t)(c) * BK * NTOTW; \
      uint32_t db = so + OFF_B + krL * 512 + qL * 128; \
      _Pragma("unroll") for (int j = 0; j < 8; j++) \
          cp16(db + (((uint32_t)j ^ swzL) << 4), bs + j * 8); } \
    if (tid < 128) { const __half* as = srcpA + (size_t)(c) * BK; \
      uint32_t da = so + (uint32_t)tid * 128; \
      _Pragma("unroll") for (int j = 0; j < 8; j++) \
          cp16(da + (((uint32_t)j ^ swrA) << 4), as + j * 8); } \
} while (0)

    // ---- fragment addressing: 8 warps = 2 (M) x 4 (N), warp tile 64x64 ----
    const int lane = tid & 31, wid = tid >> 5;
    const int wm = wid >> 2, wn = wid & 3;
    // A (normal ldsm): lanes 0-15 rows, lanes 16-31 second k-chunk
    const uint32_t rA  = lane & 15;
    const uint32_t cA  = lane >> 4;
    const uint32_t swA = rA & 7;
    uint32_t rowA_s[4];
#pragma unroll
    for (int i = 0; i < 4; i++) rowA_s[i] = (uint32_t)(wm * 64 + i * 16 + rA) * 128;
    // B (ldsm.trans on [k][n]): matrices (k0,n0),(k8,n0),(k0,n8),(k8,n8)
    const uint32_t krB  = (uint32_t)((lane & 7) + ((lane >> 3) & 1) * 8);   // 0..15
    const uint32_t nsel = (uint32_t)(lane >> 4);                            // 0..1
    const uint32_t swzB = krB & 7;
    const uint32_t cbB  = (uint32_t)(wn * 8) + nsel;                        // 16B-chunk base
    const uint32_t bB   = OFF_B + krB * 512;

    float C[4][8][4];
#pragma unroll
    for (int i = 0; i < 4; i++)
#pragma unroll
        for (int j = 0; j < 8; j++)
#pragma unroll
            for (int q = 0; q < 4; q++) C[i][j][q] = 0.f;

    LOAD_STAGE(0); CP_COMMIT();
    LOAD_STAGE(1); CP_COMMIT();

    for (int c = 0; c < NCH; c++) {
        CP_WAIT(1);
        __syncthreads();
        // buffer (c+2)%3 == (c-1)%3 is free (all warps finished chunk c-1)
        if (c + 2 < NCH) LOAD_STAGE(c + 2);
        CP_COMMIT();

        const uint32_t buf = S + OFF_TILE + (uint32_t)(c % NSTAGE) * STAGE_BYTES;
#pragma unroll
        for (int s = 0; s < 4; s++) {          // 4 x k16 per 64-chunk
            const uint32_t kc = 2 * s;
            uint32_t A[4][4], B[4][4];
#pragma unroll
            for (int i = 0; i < 4; i++)
                ldsm4(A[i], buf + rowA_s[i] + (((kc + cA) ^ swA) << 4));
#pragma unroll
            for (int jj = 0; jj < 4; jj++)
                ldsm4t(B[jj], buf + bB + s * 8192 + (((cbB + jj * 2) ^ swzB) << 4));
#pragma unroll
            for (int i = 0; i < 4; i++)
#pragma unroll
                for (int j = 0; j < 8; j++)
                    mma16816(C[i][j], A[i], &B[j >> 1][(j & 1) * 2]);
        }
    }
#undef LOAD_STAGE

    // -------- epilogue --------
    const int gcol0 = n0 + wn * 64;
#pragma unroll
    for (int i = 0; i < 4; i++) {
        const int rbase = wm * 64 + i * 16 + (lane >> 2);
#pragma unroll
        for (int half = 0; half < 2; half++) {
            const int rr = rbase + 8 * half;
            const int m  = m0 + rr;
            if (m >= cnt) continue;
            if (MODE == 0) {
                const size_t pb = (size_t)(base + m) * HH;
#pragma unroll
                for (int j = 0; j < 8; j++) {
                    const int cc = gcol0 + j * 8 + (lane & 3) * 2;
                    float v0 = fmaxf(C[i][j][2 * half]     + bias[e * HH + cc],     0.f);
                    float v1 = fmaxf(C[i][j][2 * half + 1] + bias[e * HH + cc + 1], 0.f);
                    *(__half2*)(&g_h[pb + cc]) = __floats2half2_rn(v0, v1);
                }
            } else {
                const int t = tok[rr];
                const float w = g_topw[t];
                float* op = out + (size_t)t * DD;
#pragma unroll
                for (int j = 0; j < 8; j++) {
                    const int cc = gcol0 + j * 8 + (lane & 3) * 2;
                    float2 v;
                    v.x = w * (C[i][j][2 * half]     + bias[e * DD + cc]);
                    v.y = w * (C[i][j][2 * half + 1] + bias[e * DD + cc + 1]);
                    *(float2*)(op + cc) = v;
                }
            }
        }
    }
}

// -------------------- launch --------------------
extern "C" void kernel_launch(void* const* d_in, const int* in_sizes, int n_in,
                              void* d_out, int out_size) {
    const float* x  = (const float*)d_in[0];
    const float* Wg = (const float*)d_in[1];
    const float* bg = (const float*)d_in[2];
    const float* W1 = (const float*)d_in[3];
    const float* b1 = (const float*)d_in[4];
    const float* W2 = (const float*)d_in[5];
    const float* b2 = (const float*)d_in[6];
    float* out = (float*)d_out;
    float* gw  = out + (size_t)NTOK * DD;   // gate_weights appended after `out`

    cudaFuncSetAttribute(moe_gemm<0>, cudaFuncAttributeMaxDynamicSharedMemorySize, SMEM_TOTAL);
    cudaFuncSetAttribute(moe_gemm<1>, cudaFuncAttributeMaxDynamicSharedMemorySize, SMEM_TOTAL);

    gate_kernel<<<NTOK / 8, 256>>>(x, Wg, bg, gw);            // 1 (fused x->fp16 + counts)
    scan_kernel<<<1, 1>>>();                                  // 2 (offs/cursor + re-zero counts)
    prep_kernel<<<32832, 256>>>(W1, W2);                      // 3 (stream convert + scatter)
    moe_gemm<0><<<dim3(HH / BN, NTOK / BM, EE), 256, SMEM_TOTAL>>>(b1, nullptr);  // 4 <- ncu
    moe_gemm<1><<<dim3(DD / BN, NTOK / BM, EE), 256, SMEM_TOTAL>>>(b2, out);      // 5
}

// round 14
// speedup vs baseline: 1.1656x; 1.1309x over previous
#include <cuda_runtime.h>
#include <cuda_fp16.h>
#include <math.h>
#include <stdint.h>

// Problem constants
#define NB 8
#define LL 2048
#define NTOK (NB*LL)        // 16384
#define DD 1024
#define EE 8
#define HH 2048

#define BM 128
#define BN 256
#define BK 64
#define NSTAGE 3
#define ATILE_BYTES 16384       // 128 rows x 128B
#define BTILE_BYTES 32768       // 256 rows x 128B
#define STAGE_BYTES (ATILE_BYTES + BTILE_BYTES)   // 49152
#define OFF_B ATILE_BYTES
#define OFF_TOK 0
#define OFF_TILE 1024
#define SMEM_TOTAL (OFF_TILE + NSTAGE * STAGE_BYTES)   // 148480

// -------------------- device scratch (no allocs allowed) --------------------
__device__ __half g_xh[(size_t)NTOK * DD];
__device__ __half g_w1h[(size_t)EE * HH * DD];   // [E][H][D]  (W1^T)
__device__ __half g_w2h[(size_t)EE * DD * HH];   // [E][D][H]  (W2^T)
__device__ __half g_h[(size_t)NTOK * HH];        // permuted hidden
__device__ int   g_perm[NTOK];
__device__ int   g_topidx[NTOK];
__device__ float g_topw[NTOK];
__device__ int   g_counts[EE];   // zero at module load; scan re-zeros after use
__device__ int   g_offs[EE + 1];
__device__ int   g_cursor[EE];

// -------------------- PTX helpers (all non-'a' features) --------------------
__device__ __forceinline__ uint32_t smem_u32(const void* p) {
    uint32_t a;
    asm("{ .reg .u64 t; cvta.to.shared.u64 t, %1; cvt.u32.u64 %0, t; }" : "=r"(a) : "l"(p));
    return a;
}
__device__ __forceinline__ void cp16(uint32_t dst, const void* src) {
    asm volatile("cp.async.cg.shared.global [%0], [%1], 16;" :: "r"(dst), "l"(src));
}
#define CP_COMMIT() asm volatile("cp.async.commit_group;" ::: "memory")
#define CP_WAIT(n)  asm volatile("cp.async.wait_group %0;" :: "n"(n) : "memory")

__device__ __forceinline__ void ldsm4(uint32_t* r, uint32_t addr) {
    asm volatile("ldmatrix.sync.aligned.m8n8.x4.shared.b16 {%0,%1,%2,%3}, [%4];"
                 : "=r"(r[0]), "=r"(r[1]), "=r"(r[2]), "=r"(r[3]) : "r"(addr));
}
__device__ __forceinline__ void mma16816(float* c, const uint32_t* a, const uint32_t* b) {
    asm volatile("mma.sync.aligned.m16n8k16.row.col.f32.f16.f16.f32 "
        "{%0,%1,%2,%3}, {%4,%5,%6,%7}, {%8,%9}, {%0,%1,%2,%3};"
        : "+f"(c[0]), "+f"(c[1]), "+f"(c[2]), "+f"(c[3])
        : "r"(a[0]), "r"(a[1]), "r"(a[2]), "r"(a[3]), "r"(b[0]), "r"(b[1]));
}

// ------- gating (fused x->fp16 conversion; Wg staged transposed in smem) -----
__global__ void gate_kernel(const float* __restrict__ x,
                            const float* __restrict__ Wg,
                            const float* __restrict__ bg,
                            float* __restrict__ gw_out) {
    __shared__ float wgs[EE][DD];        // 32KB, WgT: [expert][k]
    const int tid = threadIdx.x;
    // cooperative transposed load of all of Wg (coalesced float4 reads)
    for (int i = tid; i < DD * EE / 4; i += 256) {
        float4 v = ((const float4*)Wg)[i];
        int k = i >> 1, e0 = (i & 1) * 4;
        wgs[e0 + 0][k] = v.x;
        wgs[e0 + 1][k] = v.y;
        wgs[e0 + 2][k] = v.z;
        wgs[e0 + 3][k] = v.w;
    }
    __syncthreads();

    int warp = tid >> 5;
    int lane = tid & 31;
    int t = blockIdx.x * 8 + warp;
    if (t >= NTOK) return;

    const float* xr = x + (size_t)t * DD;
    float xv[32];
#pragma unroll
    for (int i = 0; i < 32; i++) xv[i] = xr[lane + 32 * i];

    __half* xh = g_xh + (size_t)t * DD;
#pragma unroll
    for (int i = 0; i < 32; i++) xh[lane + 32 * i] = __float2half_rn(xv[i]);

    float logit[EE];
#pragma unroll
    for (int e = 0; e < EE; e++) {
        float s = 0.f;
#pragma unroll
        for (int i = 0; i < 32; i++) s += xv[i] * wgs[e][lane + 32 * i];
#pragma unroll
        for (int o = 16; o > 0; o >>= 1) s += __shfl_xor_sync(0xffffffffu, s, o);
        logit[e] = s + bg[e];
    }

    if (lane == 0) {
        float mx = logit[0]; int bi = 0;
#pragma unroll
        for (int e = 1; e < EE; e++) if (logit[e] > mx) { mx = logit[e]; bi = e; }
        float p[EE]; float se = 0.f;
#pragma unroll
        for (int e = 0; e < EE; e++) { p[e] = expf(logit[e] - mx); se += p[e]; }
        float inv = 1.f / se;
#pragma unroll
        for (int e = 0; e < EE; e++) gw_out[(size_t)t * EE + e] = p[e] * inv;
        g_topidx[t] = bi;
        g_topw[t]  = p[bi] * inv;
        atomicAdd(&g_counts[bi], 1);
    }
}

// -------------------- scan: offsets + cursor, then re-zero counts ------------
__global__ void scan_kernel() {
    int s = 0;
    g_offs[0] = 0;
    for (int e = 0; e < EE; e++) {
        g_cursor[e] = s;
        s += g_counts[e];
        g_offs[e + 1] = s;
        g_counts[e] = 0;          // ready for next kernel_launch invocation
    }
}

// -------------------- prep: fused weight-convert/transpose + scatter ---------
__global__ void prep_kernel(const float* __restrict__ W1, const float* __restrict__ W2) {
    const int bid = blockIdx.x;
    const int tid = threadIdx.x;
    if (bid >= 65536) {
        int t = (bid - 65536) * 256 + tid;
        if (t < NTOK) {
            int e = g_topidx[t];
            int pos = atomicAdd(&g_cursor[e], 1);
            g_perm[pos] = t;
        }
        return;
    }
    const int bx = bid & 63, by = (bid >> 6) & 63, bz = bid >> 12;
    const float* src;
    __half* dh;
    int K, N;
    if (bz < EE) {
        src = W1 + (size_t)bz * DD * HH; dh = g_w1h + (size_t)bz * HH * DD;
        K = DD; N = HH;
        if (by >= K / 32) return;
    } else {
        int e = bz - EE;
        src = W2 + (size_t)e * HH * DD; dh = g_w2h + (size_t)e * DD * HH;
        K = HH; N = DD;
        if (bx >= N / 32) return;
    }
    __shared__ float t[32][33];
    const int tx = tid & 31, ty = tid >> 5;
    const int n0 = bx * 32, k0 = by * 32;
#pragma unroll
    for (int i = 0; i < 4; i++)
        t[ty + i * 8][tx] = src[(size_t)(k0 + ty + i * 8) * N + n0 + tx];
    __syncthreads();
#pragma unroll
    for (int i = 0; i < 4; i++) {
        float v = t[tx][ty + i * 8];
        size_t o = (size_t)(n0 + ty + i * 8) * K + (k0 + tx);
        dh[o] = __float2half_rn(v);
    }
}

// -------------------- mma.sync MoE GEMM (fp16), 128x256 tile, warp 64x64 -----
// SMEM rows 128B = 64 fp16 (k-dim), 16B chunks swizzled by (row&7).
#define LOAD_ROW(ptr, db) do { \
    cp16((db) + ((0u ^ swr) << 4), (ptr) + 0);  cp16((db) + ((1u ^ swr) << 4), (ptr) + 8); \
    cp16((db) + ((2u ^ swr) << 4), (ptr) + 16); cp16((db) + ((3u ^ swr) << 4), (ptr) + 24); \
    cp16((db) + ((4u ^ swr) << 4), (ptr) + 32); cp16((db) + ((5u ^ swr) << 4), (ptr) + 40); \
    cp16((db) + ((6u ^ swr) << 4), (ptr) + 48); cp16((db) + ((7u ^ swr) << 4), (ptr) + 56); \
} while (0)

#define LOAD_STAGE(c) do { \
    uint32_t so = OFF_TILE + ((c) % NSTAGE) * STAGE_BYTES; \
    LOAD_ROW(srcp0 + (size_t)(c) * BK, S + so + dst0); \
    if (tid < 128) LOAD_ROW(srcp1 + (size_t)(c) * BK, S + so + dst1); \
} while (0)

template<int MODE>
__global__ __launch_bounds__(256, 1)
void moe_gemm(const float* __restrict__ bias, float* __restrict__ out) {
    constexpr int KTOT = (MODE == 0) ? DD : HH;
    constexpr int NROW = (MODE == 0) ? HH : DD;
    constexpr int NCH  = KTOT / BK;       // 16 or 32

    const int e    = blockIdx.z;
    const int base = g_offs[e];
    const int cnt  = g_offs[e + 1] - base;
    const int m0   = blockIdx.y * BM;
    if (m0 >= cnt) return;
    const int n0   = blockIdx.x * BN;

    extern __shared__ char smem[];
    const uint32_t S = smem_u32(smem);
    int* tok = (int*)(smem + OFF_TOK);
    const int tid = threadIdx.x;

    if (tid < 128) {
        int m = m0 + tid; if (m >= cnt) m = cnt - 1;
        tok[tid] = g_perm[base + m];
    }
    __syncthreads();

    // ---- loader setup ----
    const __half* Abase = (MODE == 0) ? g_xh : g_h;
    const __half* Wbase = (MODE == 0) ? g_w1h : g_w2h;
    const __half* srcp0;
    const __half* srcp1 = nullptr;
    uint32_t dst0, dst1 = 0;
    const uint32_t swr = (uint32_t)(tid & 7);
    if (tid < 128) {
        size_t rowA;
        if (MODE == 0) rowA = (size_t)tok[tid];
        else { int m = m0 + tid; if (m >= cnt) m = cnt - 1; rowA = (size_t)(base + m); }
        srcp0 = Abase + rowA * KTOT;
        dst0  = (uint32_t)tid * 128;                       // A region
        srcp1 = Wbase + ((size_t)e * NROW + n0 + 128 + tid) * KTOT;
        dst1  = OFF_B + (uint32_t)(128 + tid) * 128;       // B rows 128-255
    } else {
        srcp0 = Wbase + ((size_t)e * NROW + n0 + (tid - 128)) * KTOT;
        dst0  = OFF_B + (uint32_t)(tid - 128) * 128;       // B rows 0-127
    }

    // ---- fragment addressing: 8 warps = 2 (M) x 4 (N), warp tile 64x64 ----
    const int lane = tid & 31, wid = tid >> 5;
    const int wm = wid >> 2, wn = wid & 3;
    const uint32_t rA  = lane & 15;
    const uint32_t cA  = lane >> 4;
    const uint32_t swA = rA & 7;
    uint32_t rowA_s[4];
#pragma unroll
    for (int i = 0; i < 4; i++) rowA_s[i] = (uint32_t)(wm * 64 + i * 16 + rA) * 128;
    const uint32_t rB  = (lane & 7) | ((lane >> 1) & 8);
    const uint32_t cB  = (lane >> 3) & 1;
    const uint32_t swB = rB & 7;
    uint32_t rowB_s[4];
#pragma unroll
    for (int jj = 0; jj < 4; jj++) rowB_s[jj] = OFF_B + (uint32_t)(wn * 64 + jj * 16 + rB) * 128;

    float C[4][8][4];
#pragma unroll
    for (int i = 0; i < 4; i++)
#pragma unroll
        for (int j = 0; j < 8; j++)
#pragma unroll
            for (int q = 0; q < 4; q++) C[i][j][q] = 0.f;

    LOAD_STAGE(0); CP_COMMIT();
    LOAD_STAGE(1); CP_COMMIT();

    for (int c = 0; c < NCH; c++) {
        CP_WAIT(1);
        __syncthreads();
        if (c + 2 < NCH) LOAD_STAGE(c + 2);
        CP_COMMIT();

        const uint32_t buf = S + OFF_TILE + (uint32_t)(c % NSTAGE) * STAGE_BYTES;
#pragma unroll
        for (int s = 0; s < 4; s++) {          // 4 x k16 per 64-chunk
            const uint32_t kc = 2 * s;
            uint32_t A[4][4], B[4][4];
#pragma unroll
            for (int i = 0; i < 4; i++)
                ldsm4(A[i], buf + rowA_s[i] + (((kc + cA) ^ swA) << 4));
#pragma unroll
            for (int jj = 0; jj < 4; jj++)
                ldsm4(B[jj], buf + rowB_s[jj] + (((kc + cB) ^ swB) << 4));
#pragma unroll
            for (int i = 0; i < 4; i++)
#pragma unroll
                for (int j = 0; j < 8; j++)
                    mma16816(C[i][j], A[i], &B[j >> 1][(j & 1) * 2]);
        }
    }

    // -------- epilogue --------
    const int gcol0 = n0 + wn * 64;
#pragma unroll
    for (int i = 0; i < 4; i++) {
        const int rbase = wm * 64 + i * 16 + (lane >> 2);
#pragma unroll
        for (int half = 0; half < 2; half++) {
            const int rr = rbase + 8 * half;
            const int m  = m0 + rr;
            if (m >= cnt) continue;
            if (MODE == 0) {
                const size_t pb = (size_t)(base + m) * HH;
#pragma unroll
                for (int j = 0; j < 8; j++) {
                    const int cc = gcol0 + j * 8 + (lane & 3) * 2;
                    float v0 = fmaxf(C[i][j][2 * half]     + bias[e * HH + cc],     0.f);
                    float v1 = fmaxf(C[i][j][2 * half + 1] + bias[e * HH + cc + 1], 0.f);
                    *(__half2*)(&g_h[pb + cc]) = __floats2half2_rn(v0, v1);
                }
            } else {
                const int t = tok[rr];
                const float w = g_topw[t];
                float* op = out + (size_t)t * DD;
#pragma unroll
                for (int j = 0; j < 8; j++) {
                    const int cc = gcol0 + j * 8 + (lane & 3) * 2;
                    float2 v;
                    v.x = w * (C[i][j][2 * half]     + bias[e * DD + cc]);
                    v.y = w * (C[i][j][2 * half + 1] + bias[e * DD + cc + 1]);
                    *(float2*)(op + cc) = v;
                }
            }
        }
    }
}

// -------------------- launch --------------------
extern "C" void kernel_launch(void* const* d_in, const int* in_sizes, int n_in,
                              void* d_out, int out_size) {
    const float* x  = (const float*)d_in[0];
    const float* Wg = (const float*)d_in[1];
    const float* bg = (const float*)d_in[2];
    const float* W1 = (const float*)d_in[3];
    const float* b1 = (const float*)d_in[4];
    const float* W2 = (const float*)d_in[5];
    const float* b2 = (const float*)d_in[6];
    float* out = (float*)d_out;
    float* gw  = out + (size_t)NTOK * DD;   // gate_weights appended after `out`

    cudaFuncSetAttribute(moe_gemm<0>, cudaFuncAttributeMaxDynamicSharedMemorySize, SMEM_TOTAL);
    cudaFuncSetAttribute(moe_gemm<1>, cudaFuncAttributeMaxDynamicSharedMemorySize, SMEM_TOTAL);

    gate_kernel<<<NTOK / 8, 256>>>(x, Wg, bg, gw);            // 1 (smem WgT + x->fp16)
    scan_kernel<<<1, 1>>>();                                  // 2 (offs/cursor + re-zero counts)
    prep_kernel<<<65600, 256>>>(W1, W2);                      // 3 (convw + scatter fused)
    moe_gemm<0><<<dim3(HH / BN, NTOK / BM, EE), 256, SMEM_TOTAL>>>(b1, nullptr);  // 4 <- ncu
    moe_gemm<1><<<dim3(DD / BN, NTOK / BM, EE), 256, SMEM_TOTAL>>>(b2, out);      // 5
}